// round 12
// baseline (speedup 1.0000x reference)
#include <cuda_runtime.h>
#include <cuda_bf16.h>

// Problem constants
// T=2048, B=2, E=1024, H=16, D=64, BH=32
#define TT   2048
#define BB   2
#define EE   1024
#define HH   16
#define DD   64
#define BH   32

#define DINLINE __device__ __forceinline__

// ---------------- scratch (device globals; no allocations allowed) ----------
__device__ float g_q[(size_t)BH * TT * DD];     // [bh][t][d], tf32-rounded, pre-scaled by 1/8
__device__ float g_k[(size_t)BH * TT * DD];     // [bh][s][d], tf32-rounded
__device__ float g_v[(size_t)BH * TT * DD];     // [bh][s][d], tf32-rounded
__device__ float g_s[(size_t)BH * TT * TT];     // [bh][t][s] unnormalized exp(score) (tf32)
__device__ float g_l[(size_t)BH * TT];          // [bh][t] 1 / row-sum
__device__ float g_ctx[(size_t)(TT * BB) * EE]; // [t*B+b][e], tf32-rounded

// ---------------- helpers ----------------------------------------------------
DINLINE unsigned f2tf(float x) {
    unsigned u;
    asm("cvt.rna.tf32.f32 %0, %1;" : "=r"(u) : "f"(x));
    return u;
}
DINLINE float rtf(float x) { return __uint_as_float(f2tf(x)); }

DINLINE void mma_tf32(float c[4], const unsigned a[4], const unsigned b[2]) {
    asm volatile(
        "mma.sync.aligned.m16n8k8.row.col.f32.tf32.tf32.f32 "
        "{%0,%1,%2,%3}, {%4,%5,%6,%7}, {%8,%9}, {%0,%1,%2,%3};\n"
        : "+f"(c[0]), "+f"(c[1]), "+f"(c[2]), "+f"(c[3])
        : "r"(a[0]), "r"(a[1]), "r"(a[2]), "r"(a[3]), "r"(b[0]), "r"(b[1]));
}

DINLINE unsigned sm_u32(const void* p) {
    unsigned r;
    asm("{ .reg .u64 t; cvta.to.shared.u64 t, %1; cvt.u32.u64 %0, t; }"
        : "=r"(r) : "l"(p));
    return r;
}
DINLINE void cpa16(unsigned s, const void* g) {
    asm volatile("cp.async.cg.shared.global [%0], [%1], 16;\n" :: "r"(s), "l"(g));
}
#define CPA_COMMIT() asm volatile("cp.async.commit_group;\n" ::: "memory")
#define CPA_WAIT1()  asm volatile("cp.async.wait_group 1;\n"  ::: "memory")
#define CPA_WAIT0()  asm volatile("cp.async.wait_group 0;\n"  ::: "memory")

// ---------------- Kernel A/E: projection GEMM  C = A * W^T + bias ------------
// A: [M,1024] row-major (MODE 0: query as rows m=t*B+b; MODE 1: g_ctx)
// W: [N,1024] row-major.  Block tile 128x128, BK=16, 128 threads, 4 warps
// (2x2), warp tile 64x64, m16n8k8 tf32 mma.  cp.async 3-stage pipeline,
// one __syncthreads per k-tile.  2 CTAs/SM.
// MODE 0: N=3072, epilogue scatters into g_q/g_k/g_v (q scaled by 1/8).
// MODE 1: N=1024, epilogue writes out = c + bias to Cout[m*1024+n].
//
// smem per stage: As 128x20 + Bs 128x20 floats = 20480 B; 3 stages = 61440 B.
#define PROJ_SMEM_BYTES 61440

template <int MODE>
__global__ void __launch_bounds__(128, 2) proj_gemm(const float* __restrict__ Ain,
                                                    const float* __restrict__ W,
                                                    const float* __restrict__ bias,
                                                    float* __restrict__ Cout) {
    extern __shared__ float psm[];
    const unsigned smb = sm_u32(psm);

    const int tid = threadIdx.x;
    const int m0  = blockIdx.y * 128;
    const int n0  = blockIdx.x * 128;

    const float* A  = (MODE == 1) ? g_ctx : Ain;
    const float* gA = A + (size_t)(m0 + tid) * 1024;
    const float* gB = W + (size_t)(n0 + tid) * 1024;

    const int lane = tid & 31, w = tid >> 5;
    const int wm = (w >> 1) * 64;   // 0 / 64
    const int wn = (w & 1) * 64;    // 0 / 64
    const int gp = lane >> 2, tq = lane & 3;

    float acc[4][8][4];
    #pragma unroll
    for (int i = 0; i < 4; i++)
        #pragma unroll
        for (int j = 0; j < 8; j++)
            #pragma unroll
            for (int k = 0; k < 4; k++) acc[i][j][k] = 0.f;

    // stage k-tile kt into buffer kt%3 (each thread: row tid of A and of B)
    auto stage = [&](int kt) {
        const int st = kt - (kt / 3) * 3;
        unsigned dA = smb + (unsigned)st * 20480u + (unsigned)tid * 80u;
        unsigned dB = dA + 10240u;
        const float* sA = gA + kt * 16;
        const float* sB = gB + kt * 16;
        cpa16(dA,       sA);
        cpa16(dA + 16u, sA + 4);
        cpa16(dA + 32u, sA + 8);
        cpa16(dA + 48u, sA + 12);
        cpa16(dB,       sB);
        cpa16(dB + 16u, sB + 4);
        cpa16(dB + 32u, sB + 8);
        cpa16(dB + 48u, sB + 12);
        CPA_COMMIT();
    };

    const int KT = 64;
    stage(0);
    stage(1);

    for (int kt = 0; kt < KT; ++kt) {
        if (kt < KT - 1) CPA_WAIT1(); else CPA_WAIT0();
        __syncthreads();             // tile kt visible to all; prior compute done
        if (kt + 2 < KT) stage(kt + 2);

        const int st = kt - (kt / 3) * 3;
        const float* As = psm + st * 5120;
        const float* Bs = As + 2560;

        #pragma unroll
        for (int kk = 0; kk < 16; kk += 8) {
            unsigned a[4][4], b[8][2];
            #pragma unroll
            for (int mi = 0; mi < 4; mi++) {
                int r = wm + mi * 16 + gp;
                a[mi][0] = f2tf(As[r * 20 + kk + tq]);
                a[mi][1] = f2tf(As[(r + 8) * 20 + kk + tq]);
                a[mi][2] = f2tf(As[r * 20 + kk + tq + 4]);
                a[mi][3] = f2tf(As[(r + 8) * 20 + kk + tq + 4]);
            }
            #pragma unroll
            for (int ni = 0; ni < 8; ni++) {
                int rn = wn + ni * 8 + gp;
                b[ni][0] = f2tf(Bs[rn * 20 + kk + tq]);
                b[ni][1] = f2tf(Bs[rn * 20 + kk + tq + 4]);
            }
            #pragma unroll
            for (int mi = 0; mi < 4; mi++)
                #pragma unroll
                for (int ni = 0; ni < 8; ni++)
                    mma_tf32(acc[mi][ni], a[mi], b[ni]);
        }
    }

    // epilogue
    #pragma unroll
    for (int mi = 0; mi < 4; mi++) {
        #pragma unroll
        for (int ni = 0; ni < 8; ni++) {
            int mrow = m0 + wm + mi * 16 + gp;
            int ncol = n0 + wn + ni * 8 + 2 * tq;
            float* c = acc[mi][ni];
            if (MODE == 0) {
                #pragma unroll
                for (int e = 0; e < 4; e++) {
                    int m = mrow + ((e >> 1) ? 8 : 0);
                    int f = ncol + (e & 1);
                    float v = c[e] + __ldg(&bias[f]);
                    int sec = f >> 10;
                    int rem = f & 1023;
                    int h = rem >> 6, d = rem & 63;
                    int t = m >> 1, bz = m & 1;
                    if (sec == 0) v *= 0.125f;   // D^-0.5
                    size_t idx = ((size_t)((bz << 4) + h) * TT + t) * DD + d;
                    float ov = rtf(v);
                    if (sec == 0)      g_q[idx] = ov;
                    else if (sec == 1) g_k[idx] = ov;
                    else               g_v[idx] = ov;
                }
            } else {
                float b0 = __ldg(&bias[ncol]);
                float b1 = __ldg(&bias[ncol + 1]);
                float2 v0 = make_float2(c[0] + b0, c[1] + b1);
                float2 v1 = make_float2(c[2] + b0, c[3] + b1);
                *(float2*)&Cout[(size_t)mrow * 1024 + ncol]       = v0;
                *(float2*)&Cout[(size_t)(mrow + 8) * 1024 + ncol] = v1;
            }
        }
    }
}

// ---------------- Fused attention: scores + exp + row-sum + AV ---------------
// One CTA per (bh, 128-row q tile). Streams K/V tiles s<=mt.
// Scores are small (|s| < ~10) by construction, so exp without max-shift is
// numerically safe and mathematically identical to softmax.
// S-phase warp tile 64x32 (2x4 warps); AV-phase warp tile 32x32 (4x2 warps).
//
// SMEM (dynamic, 174144 B): Qs[128][68] Ks[128][68] Vs[128][68] Es[128][132] Ls[4][132]
#define QS_OFF 0
#define KS_OFF 8704
#define VS_OFF 17408
#define ES_OFF 26112
#define LS_OFF 43008
#define FUSED_SMEM_BYTES (43536 * 4)

__global__ void __launch_bounds__(256, 1) attn_fused() {
    extern __shared__ float sm[];
    float* Qs = sm + QS_OFF;
    float* Ks = sm + KS_OFF;
    float* Vs = sm + VS_OFF;
    float* Es = sm + ES_OFF;
    float* Ls = sm + LS_OFF;

    const int mt = 15 - blockIdx.x;   // big tiles first
    const int bh = blockIdx.y;
    const int tid = threadIdx.x, lane = tid & 31, w = tid >> 5;
    // S-phase mapping (64x32 warp tiles)
    const int wm  = (w >> 2) * 64;
    const int wn  = (w & 3) * 32;
    // AV-phase mapping (32x32 warp tiles)
    const int wm4 = (w >> 1) * 32;
    const int wn4 = (w & 1) * 32;
    const int gp = lane >> 2, tq = lane & 3;

    // load Q tile [128][64]
    {
        const float* Qp = g_q + ((size_t)bh * TT + (size_t)mt * 128) * DD;
        #pragma unroll
        for (int j = 0; j < 8; j++) {
            int q = tid + j * 256;
            int r = q >> 4, c = (q & 15) << 2;
            *(float4*)&Qs[r * 68 + c] = *(const float4*)(Qp + (size_t)r * DD + c);
        }
    }

    float ctx[2][4][4];
    #pragma unroll
    for (int i = 0; i < 2; i++)
        #pragma unroll
        for (int j = 0; j < 4; j++)
            #pragma unroll
            for (int k = 0; k < 4; k++) ctx[i][j][k] = 0.f;
    float Lp[8] = {0.f, 0.f, 0.f, 0.f, 0.f, 0.f, 0.f, 0.f};

    for (int nt = 0; nt <= mt; ++nt) {
        __syncthreads();   // protect Qs(first iter)/Ks/Vs/Es from prior readers
        // load K/V tiles [128][64]
        {
            const float* Kp = g_k + ((size_t)bh * TT + (size_t)nt * 128) * DD;
            const float* Vp = g_v + ((size_t)bh * TT + (size_t)nt * 128) * DD;
            #pragma unroll
            for (int j = 0; j < 8; j++) {
                int q = tid + j * 256;
                int r = q >> 4, c = (q & 15) << 2;
                *(float4*)&Ks[r * 68 + c] = *(const float4*)(Kp + (size_t)r * DD + c);
                *(float4*)&Vs[r * 68 + c] = *(const float4*)(Vp + (size_t)r * DD + c);
            }
        }
        __syncthreads();

        // S = Q K^T  (warp tile 64x32)
        float sacc[4][4][4];
        #pragma unroll
        for (int i = 0; i < 4; i++)
            #pragma unroll
            for (int j = 0; j < 4; j++)
                #pragma unroll
                for (int k = 0; k < 4; k++) sacc[i][j][k] = 0.f;

        #pragma unroll
        for (int kk = 0; kk < 64; kk += 8) {
            unsigned a[4][4], b[4][2];
            #pragma unroll
            for (int mi = 0; mi < 4; mi++) {
                int r = wm + mi * 16 + gp;
                a[mi][0] = __float_as_uint(Qs[r * 68 + kk + tq]);
                a[mi][1] = __float_as_uint(Qs[(r + 8) * 68 + kk + tq]);
                a[mi][2] = __float_as_uint(Qs[r * 68 + kk + tq + 4]);
                a[mi][3] = __float_as_uint(Qs[(r + 8) * 68 + kk + tq + 4]);
            }
            #pragma unroll
            for (int ni = 0; ni < 4; ni++) {
                int rn = wn + ni * 8 + gp;
                b[ni][0] = __float_as_uint(Ks[rn * 68 + kk + tq]);
                b[ni][1] = __float_as_uint(Ks[rn * 68 + kk + tq + 4]);
            }
            #pragma unroll
            for (int mi = 0; mi < 4; mi++)
                #pragma unroll
                for (int ni = 0; ni < 4; ni++)
                    mma_tf32(sacc[mi][ni], a[mi], b[ni]);
        }

        // e = exp(S), causal mask on diagonal tile, accumulate L, stage in Es
        const bool diag = (nt == mt);
        #pragma unroll
        for (int mi = 0; mi < 4; mi++) {
            const int tl0 = wm + mi * 16 + gp;
            #pragma unroll
            for (int ni = 0; ni < 4; ni++) {
                const int sl = wn + ni * 8 + 2 * tq;
                float* c = sacc[mi][ni];
                float e0 = __expf(c[0]);
                float e1 = __expf(c[1]);
                float e2 = __expf(c[2]);
                float e3 = __expf(c[3]);
                if (diag) {
                    if (sl     > tl0)     e0 = 0.f;
                    if (sl + 1 > tl0)     e1 = 0.f;
                    if (sl     > tl0 + 8) e2 = 0.f;
                    if (sl + 1 > tl0 + 8) e3 = 0.f;
                }
                e0 = rtf(e0); e1 = rtf(e1); e2 = rtf(e2); e3 = rtf(e3);
                Lp[mi * 2]     += e0 + e1;
                Lp[mi * 2 + 1] += e2 + e3;
                *(float2*)&Es[tl0 * 132 + sl]       = make_float2(e0, e1);
                *(float2*)&Es[(tl0 + 8) * 132 + sl] = make_float2(e2, e3);
            }
        }
        __syncthreads();

        // ctx += Es(128x128) * Vs(128x64)   (warp tile 32x32)
        #pragma unroll
        for (int kk = 0; kk < 128; kk += 8) {
            unsigned a[2][4], b[4][2];
            #pragma unroll
            for (int mi = 0; mi < 2; mi++) {
                int r = wm4 + mi * 16 + gp;
                a[mi][0] = __float_as_uint(Es[r * 132 + kk + tq]);
                a[mi][1] = __float_as_uint(Es[(r + 8) * 132 + kk + tq]);
                a[mi][2] = __float_as_uint(Es[r * 132 + kk + tq + 4]);
                a[mi][3] = __float_as_uint(Es[(r + 8) * 132 + kk + tq + 4]);
            }
            #pragma unroll
            for (int ni = 0; ni < 4; ni++) {
                int n = wn4 + ni * 8 + gp;
                b[ni][0] = __float_as_uint(Vs[(kk + tq) * 68 + n]);
                b[ni][1] = __float_as_uint(Vs[(kk + tq + 4) * 68 + n]);
            }
            #pragma unroll
            for (int mi = 0; mi < 2; mi++)
                #pragma unroll
                for (int ni = 0; ni < 4; ni++)
                    mma_tf32(ctx[mi][ni], a[mi], b[ni]);
        }

        // bulk copy Es -> g_s (coalesced float4)
        {
            float* Gp = g_s + ((size_t)bh * TT + (size_t)mt * 128) * TT + (size_t)nt * 128;
            #pragma unroll
            for (int j = 0; j < 16; j++) {
                int q = tid + j * 256;
                int r = q >> 5, c = (q & 31) << 2;
                *(float4*)&Gp[(size_t)r * TT + c] = *(const float4*)&Es[r * 132 + c];
            }
        }
    }

    // reduce Lp across quad (tq) lanes
    #pragma unroll
    for (int i = 0; i < 8; i++) {
        Lp[i] += __shfl_xor_sync(0xffffffffu, Lp[i], 1);
        Lp[i] += __shfl_xor_sync(0xffffffffu, Lp[i], 2);
    }
    // cross-warp partials (4 n-warps share rows in the S mapping)
    if (tq == 0) {
        #pragma unroll
        for (int mi = 0; mi < 4; mi++) {
            Ls[(w & 3) * 132 + wm + mi * 16 + gp]     = Lp[mi * 2];
            Ls[(w & 3) * 132 + wm + mi * 16 + gp + 8] = Lp[mi * 2 + 1];
        }
    }
    __syncthreads();

    // 1/L -> g_l
    if (tid < 128) {
        float L = Ls[tid] + Ls[132 + tid] + Ls[264 + tid] + Ls[396 + tid];
        g_l[(size_t)bh * TT + (size_t)mt * 128 + tid] = 1.0f / L;
    }

    // ctx /= L, write to g_ctx[t*B+b][h*64+d]   (AV mapping)
    const int bz = bh >> 4, h = bh & 15;
    #pragma unroll
    for (int mi = 0; mi < 2; mi++) {
        const int r0 = wm4 + mi * 16 + gp, r1 = r0 + 8;
        const float iL0 = 1.0f / (Ls[r0] + Ls[132 + r0] + Ls[264 + r0] + Ls[396 + r0]);
        const float iL1 = 1.0f / (Ls[r1] + Ls[132 + r1] + Ls[264 + r1] + Ls[396 + r1]);
        #pragma unroll
        for (int ni = 0; ni < 4; ni++) {
            const int t0 = mt * 128 + r0;
            const int d0 = wn4 + ni * 8 + 2 * tq;
            float* c = ctx[mi][ni];
            size_t i0 = ((size_t)(t0 * BB + bz)) * EE + (h << 6) + d0;
            size_t i1 = ((size_t)((t0 + 8) * BB + bz)) * EE + (h << 6) + d0;
            *(float2*)&g_ctx[i0] = make_float2(rtf(c[0] * iL0), rtf(c[1] * iL0));
            *(float2*)&g_ctx[i1] = make_float2(rtf(c[2] * iL1), rtf(c[3] * iL1));
        }
    }
}

// ---------------- avg kernel: avg_w[b][t][s] = (1/H) sum_h e[bh][t][s]/L -----
__global__ void __launch_bounds__(256) avg_kernel(float* __restrict__ avg_out) {
    const int t = blockIdx.x, b = blockIdx.y, tid = threadIdx.x;
    const int len = t + 1;
    float acc[8] = {0.f, 0.f, 0.f, 0.f, 0.f, 0.f, 0.f, 0.f};

    #pragma unroll 1
    for (int h = 0; h < HH; ++h) {
        const float* rowp = g_s + ((size_t)((b << 4) + h) * TT + t) * TT;
        const float invL = g_l[(size_t)((b << 4) + h) * TT + t];
        #pragma unroll
        for (int j = 0; j < 8; j++) {
            int i = tid + (j << 8);
            if (i < len) acc[j] += rowp[i] * invL;
        }
    }
    float* dst = avg_out + ((size_t)(b * TT + t)) * TT;
    #pragma unroll
    for (int j = 0; j < 8; j++) {
        int i = tid + (j << 8);
        dst[i] = (i < len) ? acc[j] * 0.0625f : 0.f;
    }
}

// ---------------- launch ------------------------------------------------------
extern "C" void kernel_launch(void* const* d_in, const int* in_sizes, int n_in,
                              void* d_out, int out_size) {
    (void)in_sizes; (void)n_in; (void)out_size;
    const float* query = (const float*)d_in[0];
    const float* ipw   = (const float*)d_in[1];
    const float* ipb   = (const float*)d_in[2];
    const float* opw   = (const float*)d_in[3];
    const float* opb   = (const float*)d_in[4];

    float* out = (float*)d_out;                       // [T,B,E]
    float* avg = out + (size_t)TT * BB * EE;          // [B,T,T]

    cudaFuncSetAttribute(attn_fused, cudaFuncAttributeMaxDynamicSharedMemorySize,
                         FUSED_SMEM_BYTES);
    cudaFuncSetAttribute(proj_gemm<0>, cudaFuncAttributeMaxDynamicSharedMemorySize,
                         PROJ_SMEM_BYTES);
    cudaFuncSetAttribute(proj_gemm<1>, cudaFuncAttributeMaxDynamicSharedMemorySize,
                         PROJ_SMEM_BYTES);

    // 1) QKV projection: [4096,1024] x [3072,1024]^T -> scatter q/k/v (q*1/8)
    proj_gemm<0><<<dim3(3072 / 128, 4096 / 128), 128, PROJ_SMEM_BYTES>>>(query, ipw, ipb, nullptr);
    // 2) fused scores + exp + row-sum + AV (writes g_s, g_l, g_ctx)
    attn_fused<<<dim3(16, BH), 256, FUSED_SMEM_BYTES>>>();
    // 3) head-averaged attention weights
    avg_kernel<<<dim3(TT, BB), 256>>>(avg);
    // 4) out projection: [4096,1024] x [1024,1024]^T + bias -> d_out
    proj_gemm<1><<<dim3(1024 / 128, 4096 / 128), 128, PROJ_SMEM_BYTES>>>(nullptr, opw, opb, out);
}

// round 15
// speedup vs baseline: 1.0756x; 1.0756x over previous
#include <cuda_runtime.h>
#include <cuda_bf16.h>
#include <cuda_fp16.h>

// Problem constants
// T=2048, B=2, E=1024, H=16, D=64, BH=32
#define TT   2048
#define BB   2
#define EE   1024
#define HH   16
#define DD   64
#define BH   32

#define DINLINE __device__ __forceinline__

// ---------------- scratch (device globals; no allocations allowed) ----------
__device__ float  g_q[(size_t)BH * TT * DD];     // [bh][t][d], tf32-rounded, pre-scaled by 1/8
__device__ float  g_k[(size_t)BH * TT * DD];     // [bh][s][d], tf32-rounded
__device__ float  g_v[(size_t)BH * TT * DD];     // [bh][s][d], tf32-rounded
__device__ __half g_sh[(size_t)BH * TT * TT];    // [bh][t][s] unnormalized exp(score), fp16
__device__ float  g_l[(size_t)BH * TT];          // [bh][t] 1 / row-sum
__device__ float  g_ctx[(size_t)(TT * BB) * EE]; // [t*B+b][e], tf32-rounded

// ---------------- helpers ----------------------------------------------------
DINLINE unsigned f2tf(float x) {
    unsigned u;
    asm("cvt.rna.tf32.f32 %0, %1;" : "=r"(u) : "f"(x));
    return u;
}
DINLINE float rtf(float x) { return __uint_as_float(f2tf(x)); }
DINLINE float4 rtf4(float4 v) {
    return make_float4(rtf(v.x), rtf(v.y), rtf(v.z), rtf(v.w));
}

DINLINE void mma_tf32(float c[4], const unsigned a[4], const unsigned b[2]) {
    asm volatile(
        "mma.sync.aligned.m16n8k8.row.col.f32.tf32.tf32.f32 "
        "{%0,%1,%2,%3}, {%4,%5,%6,%7}, {%8,%9}, {%0,%1,%2,%3};\n"
        : "+f"(c[0]), "+f"(c[1]), "+f"(c[2]), "+f"(c[3])
        : "r"(a[0]), "r"(a[1]), "r"(a[2]), "r"(a[3]), "r"(b[0]), "r"(b[1]));
}

// ---------------- Kernel A/E: projection GEMM  C = A * W^T + bias ------------
// A: [M,1024] row-major (MODE 0: query flattened as rows m=t*B+b; MODE 1: g_ctx)
// W: [N,1024] row-major.  Tile 128x128, BK=16, 256 threads, 8 warps (2x4),
// warp tile 64x32, m16n8k8 tf32 mma, register-prefetch single smem buffer.
// Values are tf32-rounded ONCE at smem-store time; fragment loads are raw bits.
// MODE 0: N=3072, epilogue scatters into g_q/g_k/g_v (q scaled by 1/8).
// MODE 1: N=1024, epilogue writes out = c + bias to Cout[m*1024+n].
template <int MODE>
__global__ void __launch_bounds__(256) proj_gemm(const float* __restrict__ Ain,
                                                 const float* __restrict__ W,
                                                 const float* __restrict__ bias,
                                                 float* __restrict__ Cout) {
    __shared__ float As[128][20];
    __shared__ float Bs[128][20];

    const int tid  = threadIdx.x;
    const int m0   = blockIdx.y * 128;
    const int n0   = blockIdx.x * 128;
    const int lrow = tid >> 1;
    const int lcol = (tid & 1) * 8;

    const float* A  = (MODE == 1) ? g_ctx : Ain;
    const float* gA = A + (size_t)(m0 + lrow) * 1024 + lcol;
    const float* gB = W + (size_t)(n0 + lrow) * 1024 + lcol;

    const int lane = tid & 31, w = tid >> 5;
    const int wm = (w >> 2) * 64;   // 0 / 64
    const int wn = (w & 3) * 32;    // 0..96
    const int gp = lane >> 2, tq = lane & 3;

    float acc[4][4][4];
    #pragma unroll
    for (int i = 0; i < 4; i++)
        #pragma unroll
        for (int j = 0; j < 4; j++)
            #pragma unroll
            for (int k = 0; k < 4; k++) acc[i][j][k] = 0.f;

    float4 ra0 = *(const float4*)(gA);
    float4 ra1 = *(const float4*)(gA + 4);
    float4 rb0 = *(const float4*)(gB);
    float4 rb1 = *(const float4*)(gB + 4);

    const int KT = 1024 / 16;
    for (int kt = 0; kt < KT; ++kt) {
        *(float4*)&As[lrow][lcol]     = rtf4(ra0);
        *(float4*)&As[lrow][lcol + 4] = rtf4(ra1);
        *(float4*)&Bs[lrow][lcol]     = rtf4(rb0);
        *(float4*)&Bs[lrow][lcol + 4] = rtf4(rb1);
        __syncthreads();
        if (kt + 1 < KT) {
            const float* pa = gA + (kt + 1) * 16;
            const float* pb = gB + (kt + 1) * 16;
            ra0 = *(const float4*)(pa);
            ra1 = *(const float4*)(pa + 4);
            rb0 = *(const float4*)(pb);
            rb1 = *(const float4*)(pb + 4);
        }
        #pragma unroll
        for (int kk = 0; kk < 16; kk += 8) {
            unsigned a[4][4], b[4][2];
            #pragma unroll
            for (int mi = 0; mi < 4; mi++) {
                int r = wm + mi * 16 + gp;
                a[mi][0] = __float_as_uint(As[r][kk + tq]);
                a[mi][1] = __float_as_uint(As[r + 8][kk + tq]);
                a[mi][2] = __float_as_uint(As[r][kk + tq + 4]);
                a[mi][3] = __float_as_uint(As[r + 8][kk + tq + 4]);
            }
            #pragma unroll
            for (int ni = 0; ni < 4; ni++) {
                int rn = wn + ni * 8 + gp;
                b[ni][0] = __float_as_uint(Bs[rn][kk + tq]);
                b[ni][1] = __float_as_uint(Bs[rn][kk + tq + 4]);
            }
            #pragma unroll
            for (int mi = 0; mi < 4; mi++)
                #pragma unroll
                for (int ni = 0; ni < 4; ni++)
                    mma_tf32(acc[mi][ni], a[mi], b[ni]);
        }
        __syncthreads();
    }

    // epilogue
    #pragma unroll
    for (int mi = 0; mi < 4; mi++) {
        #pragma unroll
        for (int ni = 0; ni < 4; ni++) {
            int mrow = m0 + wm + mi * 16 + gp;
            int ncol = n0 + wn + ni * 8 + 2 * tq;
            float* c = acc[mi][ni];
            if (MODE == 0) {
                #pragma unroll
                for (int e = 0; e < 4; e++) {
                    int m = mrow + ((e >> 1) ? 8 : 0);
                    int f = ncol + (e & 1);
                    float v = c[e] + __ldg(&bias[f]);
                    int sec = f >> 10;
                    int rem = f & 1023;
                    int h = rem >> 6, d = rem & 63;
                    int t = m >> 1, bz = m & 1;
                    if (sec == 0) v *= 0.125f;   // D^-0.5
                    size_t idx = ((size_t)((bz << 4) + h) * TT + t) * DD + d;
                    float ov = rtf(v);
                    if (sec == 0)      g_q[idx] = ov;
                    else if (sec == 1) g_k[idx] = ov;
                    else               g_v[idx] = ov;
                }
            } else {
                float b0 = __ldg(&bias[ncol]);
                float b1 = __ldg(&bias[ncol + 1]);
                float2 v0 = make_float2(c[0] + b0, c[1] + b1);
                float2 v1 = make_float2(c[2] + b0, c[3] + b1);
                *(float2*)&Cout[(size_t)mrow * 1024 + ncol]       = v0;
                *(float2*)&Cout[(size_t)(mrow + 8) * 1024 + ncol] = v1;
            }
        }
    }
}

// ---------------- Fused attention: scores + exp + row-sum + AV ---------------
// One CTA per (bh, 128-row q tile). Streams K/V tiles s<=mt.
// Scores are small (|s| < ~10) by construction, so exp without max-shift is
// numerically safe and mathematically identical to softmax.
// S-phase warp tile 64x32 (2x4 warps); AV-phase warp tile 32x32 (4x2 warps).
// e is written to g_sh in fp16 (only consumed by the avg kernel).
//
// SMEM (dynamic, 174144 B): Qs[128][68] Ks[128][68] Vs[128][68] Es[128][132] Ls[4][132]
#define QS_OFF 0
#define KS_OFF 8704
#define VS_OFF 17408
#define ES_OFF 26112
#define LS_OFF 43008
#define FUSED_SMEM_BYTES (43536 * 4)

__global__ void __launch_bounds__(256, 1) attn_fused() {
    extern __shared__ float sm[];
    float* Qs = sm + QS_OFF;
    float* Ks = sm + KS_OFF;
    float* Vs = sm + VS_OFF;
    float* Es = sm + ES_OFF;
    float* Ls = sm + LS_OFF;

    const int mt = 15 - blockIdx.x;   // big tiles first
    const int bh = blockIdx.y;
    const int tid = threadIdx.x, lane = tid & 31, w = tid >> 5;
    // S-phase mapping (64x32 warp tiles)
    const int wm  = (w >> 2) * 64;
    const int wn  = (w & 3) * 32;
    // AV-phase mapping (32x32 warp tiles)
    const int wm4 = (w >> 1) * 32;
    const int wn4 = (w & 1) * 32;
    const int gp = lane >> 2, tq = lane & 3;

    // load Q tile [128][64]
    {
        const float* Qp = g_q + ((size_t)bh * TT + (size_t)mt * 128) * DD;
        #pragma unroll
        for (int j = 0; j < 8; j++) {
            int q = tid + j * 256;
            int r = q >> 4, c = (q & 15) << 2;
            *(float4*)&Qs[r * 68 + c] = *(const float4*)(Qp + (size_t)r * DD + c);
        }
    }

    float ctx[2][4][4];
    #pragma unroll
    for (int i = 0; i < 2; i++)
        #pragma unroll
        for (int j = 0; j < 4; j++)
            #pragma unroll
            for (int k = 0; k < 4; k++) ctx[i][j][k] = 0.f;
    float Lp[8] = {0.f, 0.f, 0.f, 0.f, 0.f, 0.f, 0.f, 0.f};

    for (int nt = 0; nt <= mt; ++nt) {
        __syncthreads();   // protect Qs(first iter)/Ks/Vs/Es from prior readers
        // load K/V tiles [128][64]
        {
            const float* Kp = g_k + ((size_t)bh * TT + (size_t)nt * 128) * DD;
            const float* Vp = g_v + ((size_t)bh * TT + (size_t)nt * 128) * DD;
            #pragma unroll
            for (int j = 0; j < 8; j++) {
                int q = tid + j * 256;
                int r = q >> 4, c = (q & 15) << 2;
                *(float4*)&Ks[r * 68 + c] = *(const float4*)(Kp + (size_t)r * DD + c);
                *(float4*)&Vs[r * 68 + c] = *(const float4*)(Vp + (size_t)r * DD + c);
            }
        }
        __syncthreads();

        // S = Q K^T  (warp tile 64x32)
        float sacc[4][4][4];
        #pragma unroll
        for (int i = 0; i < 4; i++)
            #pragma unroll
            for (int j = 0; j < 4; j++)
                #pragma unroll
                for (int k = 0; k < 4; k++) sacc[i][j][k] = 0.f;

        #pragma unroll
        for (int kk = 0; kk < 64; kk += 8) {
            unsigned a[4][4], b[4][2];
            #pragma unroll
            for (int mi = 0; mi < 4; mi++) {
                int r = wm + mi * 16 + gp;
                a[mi][0] = __float_as_uint(Qs[r * 68 + kk + tq]);
                a[mi][1] = __float_as_uint(Qs[(r + 8) * 68 + kk + tq]);
                a[mi][2] = __float_as_uint(Qs[r * 68 + kk + tq + 4]);
                a[mi][3] = __float_as_uint(Qs[(r + 8) * 68 + kk + tq + 4]);
            }
            #pragma unroll
            for (int ni = 0; ni < 4; ni++) {
                int rn = wn + ni * 8 + gp;
                b[ni][0] = __float_as_uint(Ks[rn * 68 + kk + tq]);
                b[ni][1] = __float_as_uint(Ks[rn * 68 + kk + tq + 4]);
            }
            #pragma unroll
            for (int mi = 0; mi < 4; mi++)
                #pragma unroll
                for (int ni = 0; ni < 4; ni++)
                    mma_tf32(sacc[mi][ni], a[mi], b[ni]);
        }

        // e = exp(S), causal mask on diagonal tile, accumulate L, stage in Es
        const bool diag = (nt == mt);
        #pragma unroll
        for (int mi = 0; mi < 4; mi++) {
            const int tl0 = wm + mi * 16 + gp;
            #pragma unroll
            for (int ni = 0; ni < 4; ni++) {
                const int sl = wn + ni * 8 + 2 * tq;
                float* c = sacc[mi][ni];
                float e0 = __expf(c[0]);
                float e1 = __expf(c[1]);
                float e2 = __expf(c[2]);
                float e3 = __expf(c[3]);
                if (diag) {
                    if (sl     > tl0)     e0 = 0.f;
                    if (sl + 1 > tl0)     e1 = 0.f;
                    if (sl     > tl0 + 8) e2 = 0.f;
                    if (sl + 1 > tl0 + 8) e3 = 0.f;
                }
                e0 = rtf(e0); e1 = rtf(e1); e2 = rtf(e2); e3 = rtf(e3);
                Lp[mi * 2]     += e0 + e1;
                Lp[mi * 2 + 1] += e2 + e3;
                *(float2*)&Es[tl0 * 132 + sl]       = make_float2(e0, e1);
                *(float2*)&Es[(tl0 + 8) * 132 + sl] = make_float2(e2, e3);
            }
        }
        __syncthreads();

        // ctx += Es(128x128) * Vs(128x64)   (warp tile 32x32)
        #pragma unroll
        for (int kk = 0; kk < 128; kk += 8) {
            unsigned a[2][4], b[4][2];
            #pragma unroll
            for (int mi = 0; mi < 2; mi++) {
                int r = wm4 + mi * 16 + gp;
                a[mi][0] = __float_as_uint(Es[r * 132 + kk + tq]);
                a[mi][1] = __float_as_uint(Es[(r + 8) * 132 + kk + tq]);
                a[mi][2] = __float_as_uint(Es[r * 132 + kk + tq + 4]);
                a[mi][3] = __float_as_uint(Es[(r + 8) * 132 + kk + tq + 4]);
            }
            #pragma unroll
            for (int ni = 0; ni < 4; ni++) {
                int n = wn4 + ni * 8 + gp;
                b[ni][0] = __float_as_uint(Vs[(kk + tq) * 68 + n]);
                b[ni][1] = __float_as_uint(Vs[(kk + tq + 4) * 68 + n]);
            }
            #pragma unroll
            for (int mi = 0; mi < 2; mi++)
                #pragma unroll
                for (int ni = 0; ni < 4; ni++)
                    mma_tf32(ctx[mi][ni], a[mi], b[ni]);
        }

        // bulk copy Es -> g_sh (fp16, 8B per thread per step, coalesced)
        {
            __half* Gp = g_sh + ((size_t)bh * TT + (size_t)mt * 128) * TT + (size_t)nt * 128;
            #pragma unroll
            for (int j = 0; j < 16; j++) {
                int q = tid + j * 256;
                int r = q >> 5, c = (q & 31) << 2;
                float4 v = *(const float4*)&Es[r * 132 + c];
                __half2 h0 = __floats2half2_rn(v.x, v.y);
                __half2 h1 = __floats2half2_rn(v.z, v.w);
                uint2 u;
                u.x = *(unsigned*)&h0;
                u.y = *(unsigned*)&h1;
                *(uint2*)&Gp[(size_t)r * TT + c] = u;
            }
        }
    }

    // reduce Lp across quad (tq) lanes
    #pragma unroll
    for (int i = 0; i < 8; i++) {
        Lp[i] += __shfl_xor_sync(0xffffffffu, Lp[i], 1);
        Lp[i] += __shfl_xor_sync(0xffffffffu, Lp[i], 2);
    }
    // cross-warp partials (4 n-warps share rows in the S mapping)
    if (tq == 0) {
        #pragma unroll
        for (int mi = 0; mi < 4; mi++) {
            Ls[(w & 3) * 132 + wm + mi * 16 + gp]     = Lp[mi * 2];
            Ls[(w & 3) * 132 + wm + mi * 16 + gp + 8] = Lp[mi * 2 + 1];
        }
    }
    __syncthreads();

    // 1/L -> g_l
    if (tid < 128) {
        float L = Ls[tid] + Ls[132 + tid] + Ls[264 + tid] + Ls[396 + tid];
        g_l[(size_t)bh * TT + (size_t)mt * 128 + tid] = 1.0f / L;
    }

    // ctx /= L, write to g_ctx[t*B+b][h*64+d]   (AV mapping)
    const int bz = bh >> 4, h = bh & 15;
    #pragma unroll
    for (int mi = 0; mi < 2; mi++) {
        const int r0 = wm4 + mi * 16 + gp, r1 = r0 + 8;
        const float iL0 = 1.0f / (Ls[r0] + Ls[132 + r0] + Ls[264 + r0] + Ls[396 + r0]);
        const float iL1 = 1.0f / (Ls[r1] + Ls[132 + r1] + Ls[264 + r1] + Ls[396 + r1]);
        #pragma unroll
        for (int ni = 0; ni < 4; ni++) {
            const int t0 = mt * 128 + r0;
            const int d0 = wn4 + ni * 8 + 2 * tq;
            float* c = ctx[mi][ni];
            size_t i0 = ((size_t)(t0 * BB + bz)) * EE + (h << 6) + d0;
            size_t i1 = ((size_t)((t0 + 8) * BB + bz)) * EE + (h << 6) + d0;
            *(float2*)&g_ctx[i0] = make_float2(rtf(c[0] * iL0), rtf(c[1] * iL0));
            *(float2*)&g_ctx[i1] = make_float2(rtf(c[2] * iL1), rtf(c[3] * iL1));
        }
    }
}

// ---------------- avg kernel: avg_w[b][t][s] = (1/H) sum_h e[bh][t][s]/L -----
// Reads fp16 e as half2 (8B/thread/step), accumulates fp32.
__global__ void __launch_bounds__(256) avg_kernel(float* __restrict__ avg_out) {
    const int t = blockIdx.x, b = blockIdx.y, tid = threadIdx.x;
    const int len = t + 1;
    float2 acc[4];
    #pragma unroll
    for (int j = 0; j < 4; j++) acc[j] = make_float2(0.f, 0.f);

    #pragma unroll 1
    for (int h = 0; h < HH; ++h) {
        const __half2* rowp =
            (const __half2*)(g_sh + ((size_t)((b << 4) + h) * TT + t) * TT);
        const float invL = g_l[(size_t)((b << 4) + h) * TT + t];
        #pragma unroll
        for (int j = 0; j < 4; j++) {
            int i2 = tid + (j << 8);        // half2 index, cols 2*i2, 2*i2+1
            int c0 = i2 << 1;
            if (c0 < len) {
                float2 e = __half22float2(rowp[i2]);
                acc[j].x += e.x * invL;
                if (c0 + 1 < len) acc[j].y += e.y * invL;
            }
        }
    }
    float2* dst = (float2*)(avg_out + ((size_t)(b * TT + t)) * TT);
    #pragma unroll
    for (int j = 0; j < 4; j++) {
        int i2 = tid + (j << 8);
        int c0 = i2 << 1;
        float2 o;
        o.x = (c0     < len) ? acc[j].x * 0.0625f : 0.f;
        o.y = (c0 + 1 < len) ? acc[j].y * 0.0625f : 0.f;
        dst[i2] = o;
    }
}

// ---------------- launch ------------------------------------------------------
extern "C" void kernel_launch(void* const* d_in, const int* in_sizes, int n_in,
                              void* d_out, int out_size) {
    (void)in_sizes; (void)n_in; (void)out_size;
    const float* query = (const float*)d_in[0];
    const float* ipw   = (const float*)d_in[1];
    const float* ipb   = (const float*)d_in[2];
    const float* opw   = (const float*)d_in[3];
    const float* opb   = (const float*)d_in[4];

    float* out = (float*)d_out;                       // [T,B,E]
    float* avg = out + (size_t)TT * BB * EE;          // [B,T,T]

    cudaFuncSetAttribute(attn_fused, cudaFuncAttributeMaxDynamicSharedMemorySize,
                         FUSED_SMEM_BYTES);

    // 1) QKV projection: [4096,1024] x [3072,1024]^T -> scatter q/k/v (q*1/8)
    proj_gemm<0><<<dim3(3072 / 128, 4096 / 128), 256>>>(query, ipw, ipb, nullptr);
    // 2) fused scores + exp + row-sum + AV (writes g_sh fp16, g_l, g_ctx)
    attn_fused<<<dim3(16, BH), 256, FUSED_SMEM_BYTES>>>();
    // 3) head-averaged attention weights (fp16 reads)
    avg_kernel<<<dim3(TT, BB), 256>>>(avg);
    // 4) out projection: [4096,1024] x [1024,1024]^T + bias -> d_out
    proj_gemm<1><<<dim3(1024 / 128, 4096 / 128), 256>>>(nullptr, opw, opb, out);
}

// round 17
// speedup vs baseline: 1.1546x; 1.0735x over previous
#include <cuda_runtime.h>
#include <cuda_bf16.h>
#include <cuda_fp16.h>

// Problem constants
// T=2048, B=2, E=1024, H=16, D=64, BH=32
#define TT   2048
#define BB   2
#define EE   1024
#define HH   16
#define DD   64
#define BH   32

#define DINLINE __device__ __forceinline__

// ---------------- scratch (device globals; no allocations allowed) ----------
__device__ float  g_q[(size_t)BH * TT * DD];     // [bh][t][d], tf32-rounded, pre-scaled by 1/8
__device__ float  g_k[(size_t)BH * TT * DD];     // [bh][s][d], tf32-rounded
__device__ float  g_v[(size_t)BH * TT * DD];     // [bh][s][d], tf32-rounded
__device__ __half g_sh[(size_t)BH * TT * TT];    // [bh][t][s] unnormalized exp(score), fp16
__device__ float  g_l[(size_t)BH * TT];          // [bh][t] 1 / row-sum
__device__ float  g_ctx[(size_t)(TT * BB) * EE]; // [t*B+b][e], tf32-rounded

// ---------------- helpers ----------------------------------------------------
DINLINE unsigned f2tf(float x) {
    unsigned u;
    asm("cvt.rna.tf32.f32 %0, %1;" : "=r"(u) : "f"(x));
    return u;
}
DINLINE float rtf(float x) { return __uint_as_float(f2tf(x)); }

DINLINE void mma_tf32(float c[4], const unsigned a[4], const unsigned b[2]) {
    asm volatile(
        "mma.sync.aligned.m16n8k8.row.col.f32.tf32.tf32.f32 "
        "{%0,%1,%2,%3}, {%4,%5,%6,%7}, {%8,%9}, {%0,%1,%2,%3};\n"
        : "+f"(c[0]), "+f"(c[1]), "+f"(c[2]), "+f"(c[3])
        : "r"(a[0]), "r"(a[1]), "r"(a[2]), "r"(a[3]), "r"(b[0]), "r"(b[1]));
}

DINLINE unsigned sm_u32(const void* p) {
    unsigned r;
    asm("{ .reg .u64 t; cvta.to.shared.u64 t, %1; cvt.u32.u64 %0, t; }"
        : "=r"(r) : "l"(p));
    return r;
}
DINLINE void cpa16(unsigned s, const void* g) {
    asm volatile("cp.async.cg.shared.global [%0], [%1], 16;\n" :: "r"(s), "l"(g));
}
#define CPA_COMMIT() asm volatile("cp.async.commit_group;\n" ::: "memory")
#define CPA_WAIT1()  asm volatile("cp.async.wait_group 1;\n"  ::: "memory")
#define CPA_WAIT0()  asm volatile("cp.async.wait_group 0;\n"  ::: "memory")

// ---------------- Kernel A/E: projection GEMM  C = A * W^T + bias ------------
// A: [M,1024] row-major (MODE 0: query as rows m=t*B+b; MODE 1: g_ctx)
// W: [N,1024] row-major.
// Block tile 128x256, BK=32, 256 threads, 8 warps (2x4), warp tile 64x64,
// m16n8k8 tf32 mma.  cp.async 3-stage pipeline, 1 __syncthreads per k-tile.
// Inputs tf32-rounded (cvt.rna) at fragment-load time (matches R11 numerics).
// Smem row stride 36 floats: fragment loads (bank = 4*gp + tq) and cp.async
// stores (2 threads/row; each 8-lane group covers all 32 banks) conflict-free.
// MODE 0: N=3072, epilogue scatters into g_q/g_k/g_v (q scaled by 1/8).
// MODE 1: N=1024, epilogue writes out = c + bias to Cout[m*1024+n].
#define PROJ_BK 32
#define PROJ_STRIDE 36
#define PROJ_STAGE_FLOATS ((128 + 256) * PROJ_STRIDE)       // 13824
#define PROJ_STAGE_BYTES  (PROJ_STAGE_FLOATS * 4)           // 55296
#define PROJ_SMEM_BYTES   (PROJ_STAGE_BYTES * 3)            // 165888

template <int MODE>
__global__ void __launch_bounds__(256) proj_gemm(const float* __restrict__ Ain,
                                                 const float* __restrict__ W,
                                                 const float* __restrict__ bias,
                                                 float* __restrict__ Cout) {
    extern __shared__ float psm[];
    const unsigned smb = sm_u32(psm);

    const int tid = threadIdx.x;
    const int m0  = blockIdx.y * 128;
    const int n0  = blockIdx.x * 256;

    const float* A = (MODE == 1) ? g_ctx : Ain;

    // staging: 2 threads per row, 16 floats each
    const int ar = tid >> 1;            // 0..127
    const int ac = (tid & 1) * 16;      // 0 / 16
    const float* gA  = A + (size_t)(m0 + ar) * 1024 + ac;
    const float* gB0 = W + (size_t)(n0 + ar) * 1024 + ac;
    const float* gB1 = W + (size_t)(n0 + 128 + ar) * 1024 + ac;
    const unsigned sA  = smb + (unsigned)(ar * PROJ_STRIDE + ac) * 4u;
    const unsigned sB0 = smb + (unsigned)((128 + ar) * PROJ_STRIDE + ac) * 4u;
    const unsigned sB1 = sB0 + 128u * PROJ_STRIDE * 4u;

    const int lane = tid & 31, w = tid >> 5;
    const int wm = (w >> 2) * 64;    // 0 / 64
    const int wn = (w & 3) * 64;     // 0..192
    const int gp = lane >> 2, tq = lane & 3;

    float acc[4][8][4];
    #pragma unroll
    for (int i = 0; i < 4; i++)
        #pragma unroll
        for (int j = 0; j < 8; j++)
            #pragma unroll
            for (int k = 0; k < 4; k++) acc[i][j][k] = 0.f;

    auto stage = [&](int kt) {
        const int st = kt - (kt / 3) * 3;
        const unsigned off = (unsigned)st * PROJ_STAGE_BYTES;
        const float* pa = gA  + kt * PROJ_BK;
        const float* p0 = gB0 + kt * PROJ_BK;
        const float* p1 = gB1 + kt * PROJ_BK;
        cpa16(sA  + off,       pa);
        cpa16(sA  + off + 16u, pa + 4);
        cpa16(sA  + off + 32u, pa + 8);
        cpa16(sA  + off + 48u, pa + 12);
        cpa16(sB0 + off,       p0);
        cpa16(sB0 + off + 16u, p0 + 4);
        cpa16(sB0 + off + 32u, p0 + 8);
        cpa16(sB0 + off + 48u, p0 + 12);
        cpa16(sB1 + off,       p1);
        cpa16(sB1 + off + 16u, p1 + 4);
        cpa16(sB1 + off + 32u, p1 + 8);
        cpa16(sB1 + off + 48u, p1 + 12);
        CPA_COMMIT();
    };

    const int KT = 1024 / PROJ_BK;   // 32
    stage(0);
    stage(1);

    for (int kt = 0; kt < KT; ++kt) {
        if (kt < KT - 1) CPA_WAIT1(); else CPA_WAIT0();
        __syncthreads();             // tile kt visible; all warps done with kt-1
        if (kt + 2 < KT) stage(kt + 2);

        const int st = kt - (kt / 3) * 3;
        const float* As = psm + st * PROJ_STAGE_FLOATS;
        const float* Bs = As + 128 * PROJ_STRIDE;

        #pragma unroll
        for (int kk = 0; kk < PROJ_BK; kk += 8) {
            unsigned a[4][4], b[8][2];
            #pragma unroll
            for (int mi = 0; mi < 4; mi++) {
                int r = wm + mi * 16 + gp;
                a[mi][0] = f2tf(As[r * PROJ_STRIDE + kk + tq]);
                a[mi][1] = f2tf(As[(r + 8) * PROJ_STRIDE + kk + tq]);
                a[mi][2] = f2tf(As[r * PROJ_STRIDE + kk + tq + 4]);
                a[mi][3] = f2tf(As[(r + 8) * PROJ_STRIDE + kk + tq + 4]);
            }
            #pragma unroll
            for (int ni = 0; ni < 8; ni++) {
                int rn = wn + ni * 8 + gp;
                b[ni][0] = f2tf(Bs[rn * PROJ_STRIDE + kk + tq]);
                b[ni][1] = f2tf(Bs[rn * PROJ_STRIDE + kk + tq + 4]);
            }
            #pragma unroll
            for (int mi = 0; mi < 4; mi++)
                #pragma unroll
                for (int ni = 0; ni < 8; ni++)
                    mma_tf32(acc[mi][ni], a[mi], b[ni]);
        }
    }

    // epilogue
    #pragma unroll
    for (int mi = 0; mi < 4; mi++) {
        #pragma unroll
        for (int ni = 0; ni < 8; ni++) {
            int mrow = m0 + wm + mi * 16 + gp;
            int ncol = n0 + wn + ni * 8 + 2 * tq;
            float* c = acc[mi][ni];
            if (MODE == 0) {
                #pragma unroll
                for (int e = 0; e < 4; e++) {
                    int m = mrow + ((e >> 1) ? 8 : 0);
                    int f = ncol + (e & 1);
                    float v = c[e] + __ldg(&bias[f]);
                    int sec = f >> 10;
                    int rem = f & 1023;
                    int h = rem >> 6, d = rem & 63;
                    int t = m >> 1, bz = m & 1;
                    if (sec == 0) v *= 0.125f;   // D^-0.5
                    size_t idx = ((size_t)((bz << 4) + h) * TT + t) * DD + d;
                    float ov = rtf(v);
                    if (sec == 0)      g_q[idx] = ov;
                    else if (sec == 1) g_k[idx] = ov;
                    else               g_v[idx] = ov;
                }
            } else {
                float b0 = __ldg(&bias[ncol]);
                float b1 = __ldg(&bias[ncol + 1]);
                float2 v0 = make_float2(c[0] + b0, c[1] + b1);
                float2 v1 = make_float2(c[2] + b0, c[3] + b1);
                *(float2*)&Cout[(size_t)mrow * 1024 + ncol]       = v0;
                *(float2*)&Cout[(size_t)(mrow + 8) * 1024 + ncol] = v1;
            }
        }
    }
}

// ---------------- Fused attention: scores + exp + row-sum + AV ---------------
// One CTA per (bh, 128-row q tile). Streams K/V tiles s<=mt.
// Scores are small (|s| < ~10) by construction, so exp without max-shift is
// numerically safe and mathematically identical to softmax.
// S-phase warp tile 64x32 (2x4 warps); AV-phase warp tile 32x32 (4x2 warps).
// e is written to g_sh in fp16 (only consumed by the avg kernel).
//
// SMEM (dynamic, 174144 B): Qs[128][68] Ks[128][68] Vs[128][68] Es[128][132] Ls[4][132]
#define QS_OFF 0
#define KS_OFF 8704
#define VS_OFF 17408
#define ES_OFF 26112
#define LS_OFF 43008
#define FUSED_SMEM_BYTES (43536 * 4)

__global__ void __launch_bounds__(256, 1) attn_fused() {
    extern __shared__ float sm[];
    float* Qs = sm + QS_OFF;
    float* Ks = sm + KS_OFF;
    float* Vs = sm + VS_OFF;
    float* Es = sm + ES_OFF;
    float* Ls = sm + LS_OFF;

    const int mt = 15 - blockIdx.x;   // big tiles first
    const int bh = blockIdx.y;
    const int tid = threadIdx.x, lane = tid & 31, w = tid >> 5;
    // S-phase mapping (64x32 warp tiles)
    const int wm  = (w >> 2) * 64;
    const int wn  = (w & 3) * 32;
    // AV-phase mapping (32x32 warp tiles)
    const int wm4 = (w >> 1) * 32;
    const int wn4 = (w & 1) * 32;
    const int gp = lane >> 2, tq = lane & 3;

    // load Q tile [128][64]
    {
        const float* Qp = g_q + ((size_t)bh * TT + (size_t)mt * 128) * DD;
        #pragma unroll
        for (int j = 0; j < 8; j++) {
            int q = tid + j * 256;
            int r = q >> 4, c = (q & 15) << 2;
            *(float4*)&Qs[r * 68 + c] = *(const float4*)(Qp + (size_t)r * DD + c);
        }
    }

    float ctx[2][4][4];
    #pragma unroll
    for (int i = 0; i < 2; i++)
        #pragma unroll
        for (int j = 0; j < 4; j++)
            #pragma unroll
            for (int k = 0; k < 4; k++) ctx[i][j][k] = 0.f;
    float Lp[8] = {0.f, 0.f, 0.f, 0.f, 0.f, 0.f, 0.f, 0.f};

    for (int nt = 0; nt <= mt; ++nt) {
        __syncthreads();   // protect Qs(first iter)/Ks/Vs/Es from prior readers
        // load K/V tiles [128][64]
        {
            const float* Kp = g_k + ((size_t)bh * TT + (size_t)nt * 128) * DD;
            const float* Vp = g_v + ((size_t)bh * TT + (size_t)nt * 128) * DD;
            #pragma unroll
            for (int j = 0; j < 8; j++) {
                int q = tid + j * 256;
                int r = q >> 4, c = (q & 15) << 2;
                *(float4*)&Ks[r * 68 + c] = *(const float4*)(Kp + (size_t)r * DD + c);
                *(float4*)&Vs[r * 68 + c] = *(const float4*)(Vp + (size_t)r * DD + c);
            }
        }
        __syncthreads();

        // S = Q K^T  (warp tile 64x32)
        float sacc[4][4][4];
        #pragma unroll
        for (int i = 0; i < 4; i++)
            #pragma unroll
            for (int j = 0; j < 4; j++)
                #pragma unroll
                for (int k = 0; k < 4; k++) sacc[i][j][k] = 0.f;

        #pragma unroll
        for (int kk = 0; kk < 64; kk += 8) {
            unsigned a[4][4], b[4][2];
            #pragma unroll
            for (int mi = 0; mi < 4; mi++) {
                int r = wm + mi * 16 + gp;
                a[mi][0] = __float_as_uint(Qs[r * 68 + kk + tq]);
                a[mi][1] = __float_as_uint(Qs[(r + 8) * 68 + kk + tq]);
                a[mi][2] = __float_as_uint(Qs[r * 68 + kk + tq + 4]);
                a[mi][3] = __float_as_uint(Qs[(r + 8) * 68 + kk + tq + 4]);
            }
            #pragma unroll
            for (int ni = 0; ni < 4; ni++) {
                int rn = wn + ni * 8 + gp;
                b[ni][0] = __float_as_uint(Ks[rn * 68 + kk + tq]);
                b[ni][1] = __float_as_uint(Ks[rn * 68 + kk + tq + 4]);
            }
            #pragma unroll
            for (int mi = 0; mi < 4; mi++)
                #pragma unroll
                for (int ni = 0; ni < 4; ni++)
                    mma_tf32(sacc[mi][ni], a[mi], b[ni]);
        }

        // e = exp(S), causal mask on diagonal tile, accumulate L, stage in Es
        const bool diag = (nt == mt);
        #pragma unroll
        for (int mi = 0; mi < 4; mi++) {
            const int tl0 = wm + mi * 16 + gp;
            #pragma unroll
            for (int ni = 0; ni < 4; ni++) {
                const int sl = wn + ni * 8 + 2 * tq;
                float* c = sacc[mi][ni];
                float e0 = __expf(c[0]);
                float e1 = __expf(c[1]);
                float e2 = __expf(c[2]);
                float e3 = __expf(c[3]);
                if (diag) {
                    if (sl     > tl0)     e0 = 0.f;
                    if (sl + 1 > tl0)     e1 = 0.f;
                    if (sl     > tl0 + 8) e2 = 0.f;
                    if (sl + 1 > tl0 + 8) e3 = 0.f;
                }
                e0 = rtf(e0); e1 = rtf(e1); e2 = rtf(e2); e3 = rtf(e3);
                Lp[mi * 2]     += e0 + e1;
                Lp[mi * 2 + 1] += e2 + e3;
                *(float2*)&Es[tl0 * 132 + sl]       = make_float2(e0, e1);
                *(float2*)&Es[(tl0 + 8) * 132 + sl] = make_float2(e2, e3);
            }
        }
        __syncthreads();

        // ctx += Es(128x128) * Vs(128x64)   (warp tile 32x32)
        #pragma unroll
        for (int kk = 0; kk < 128; kk += 8) {
            unsigned a[2][4], b[4][2];
            #pragma unroll
            for (int mi = 0; mi < 2; mi++) {
                int r = wm4 + mi * 16 + gp;
                a[mi][0] = __float_as_uint(Es[r * 132 + kk + tq]);
                a[mi][1] = __float_as_uint(Es[(r + 8) * 132 + kk + tq]);
                a[mi][2] = __float_as_uint(Es[r * 132 + kk + tq + 4]);
                a[mi][3] = __float_as_uint(Es[(r + 8) * 132 + kk + tq + 4]);
            }
            #pragma unroll
            for (int ni = 0; ni < 4; ni++) {
                int n = wn4 + ni * 8 + gp;
                b[ni][0] = __float_as_uint(Vs[(kk + tq) * 68 + n]);
                b[ni][1] = __float_as_uint(Vs[(kk + tq + 4) * 68 + n]);
            }
            #pragma unroll
            for (int mi = 0; mi < 2; mi++)
                #pragma unroll
                for (int ni = 0; ni < 4; ni++)
                    mma_tf32(ctx[mi][ni], a[mi], b[ni]);
        }

        // bulk copy Es -> g_sh (fp16, 8B per thread per step, coalesced)
        {
            __half* Gp = g_sh + ((size_t)bh * TT + (size_t)mt * 128) * TT + (size_t)nt * 128;
            #pragma unroll
            for (int j = 0; j < 16; j++) {
                int q = tid + j * 256;
                int r = q >> 5, c = (q & 31) << 2;
                float4 v = *(const float4*)&Es[r * 132 + c];
                __half2 h0 = __floats2half2_rn(v.x, v.y);
                __half2 h1 = __floats2half2_rn(v.z, v.w);
                uint2 u;
                u.x = *(unsigned*)&h0;
                u.y = *(unsigned*)&h1;
                *(uint2*)&Gp[(size_t)r * TT + c] = u;
            }
        }
    }

    // reduce Lp across quad (tq) lanes
    #pragma unroll
    for (int i = 0; i < 8; i++) {
        Lp[i] += __shfl_xor_sync(0xffffffffu, Lp[i], 1);
        Lp[i] += __shfl_xor_sync(0xffffffffu, Lp[i], 2);
    }
    // cross-warp partials (4 n-warps share rows in the S mapping)
    if (tq == 0) {
        #pragma unroll
        for (int mi = 0; mi < 4; mi++) {
            Ls[(w & 3) * 132 + wm + mi * 16 + gp]     = Lp[mi * 2];
            Ls[(w & 3) * 132 + wm + mi * 16 + gp + 8] = Lp[mi * 2 + 1];
        }
    }
    __syncthreads();

    // 1/L -> g_l
    if (tid < 128) {
        float L = Ls[tid] + Ls[132 + tid] + Ls[264 + tid] + Ls[396 + tid];
        g_l[(size_t)bh * TT + (size_t)mt * 128 + tid] = 1.0f / L;
    }

    // ctx /= L, write to g_ctx[t*B+b][h*64+d]   (AV mapping)
    const int bz = bh >> 4, h = bh & 15;
    #pragma unroll
    for (int mi = 0; mi < 2; mi++) {
        const int r0 = wm4 + mi * 16 + gp, r1 = r0 + 8;
        const float iL0 = 1.0f / (Ls[r0] + Ls[132 + r0] + Ls[264 + r0] + Ls[396 + r0]);
        const float iL1 = 1.0f / (Ls[r1] + Ls[132 + r1] + Ls[264 + r1] + Ls[396 + r1]);
        #pragma unroll
        for (int ni = 0; ni < 4; ni++) {
            const int t0 = mt * 128 + r0;
            const int d0 = wn4 + ni * 8 + 2 * tq;
            float* c = ctx[mi][ni];
            size_t i0 = ((size_t)(t0 * BB + bz)) * EE + (h << 6) + d0;
            size_t i1 = ((size_t)((t0 + 8) * BB + bz)) * EE + (h << 6) + d0;
            *(float2*)&g_ctx[i0] = make_float2(rtf(c[0] * iL0), rtf(c[1] * iL0));
            *(float2*)&g_ctx[i1] = make_float2(rtf(c[2] * iL1), rtf(c[3] * iL1));
        }
    }
}

// ---------------- avg kernel: avg_w[b][t][s] = (1/H) sum_h e[bh][t][s]/L -----
// Reads fp16 e as half2 (8B/thread/step), accumulates fp32.
__global__ void __launch_bounds__(256) avg_kernel(float* __restrict__ avg_out) {
    const int t = blockIdx.x, b = blockIdx.y, tid = threadIdx.x;
    const int len = t + 1;
    float2 acc[4];
    #pragma unroll
    for (int j = 0; j < 4; j++) acc[j] = make_float2(0.f, 0.f);

    #pragma unroll 1
    for (int h = 0; h < HH; ++h) {
        const __half2* rowp =
            (const __half2*)(g_sh + ((size_t)((b << 4) + h) * TT + t) * TT);
        const float invL = g_l[(size_t)((b << 4) + h) * TT + t];
        #pragma unroll
        for (int j = 0; j < 4; j++) {
            int i2 = tid + (j << 8);        // half2 index, cols 2*i2, 2*i2+1
            int c0 = i2 << 1;
            if (c0 < len) {
                float2 e = __half22float2(rowp[i2]);
                acc[j].x += e.x * invL;
                if (c0 + 1 < len) acc[j].y += e.y * invL;
            }
        }
    }
    float2* dst = (float2*)(avg_out + ((size_t)(b * TT + t)) * TT);
    #pragma unroll
    for (int j = 0; j < 4; j++) {
        int i2 = tid + (j << 8);
        int c0 = i2 << 1;
        float2 o;
        o.x = (c0     < len) ? acc[j].x * 0.0625f : 0.f;
        o.y = (c0 + 1 < len) ? acc[j].y * 0.0625f : 0.f;
        dst[i2] = o;
    }
}

// ---------------- launch ------------------------------------------------------
extern "C" void kernel_launch(void* const* d_in, const int* in_sizes, int n_in,
                              void* d_out, int out_size) {
    (void)in_sizes; (void)n_in; (void)out_size;
    const float* query = (const float*)d_in[0];
    const float* ipw   = (const float*)d_in[1];
    const float* ipb   = (const float*)d_in[2];
    const float* opw   = (const float*)d_in[3];
    const float* opb   = (const float*)d_in[4];

    float* out = (float*)d_out;                       // [T,B,E]
    float* avg = out + (size_t)TT * BB * EE;          // [B,T,T]

    cudaFuncSetAttribute(attn_fused, cudaFuncAttributeMaxDynamicSharedMemorySize,
                         FUSED_SMEM_BYTES);
    cudaFuncSetAttribute(proj_gemm<0>, cudaFuncAttributeMaxDynamicSharedMemorySize,
                         PROJ_SMEM_BYTES);
    cudaFuncSetAttribute(proj_gemm<1>, cudaFuncAttributeMaxDynamicSharedMemorySize,
                         PROJ_SMEM_BYTES);

    // 1) QKV projection: [4096,1024] x [3072,1024]^T -> scatter q/k/v (q*1/8)
    proj_gemm<0><<<dim3(3072 / 256, 4096 / 128), 256, PROJ_SMEM_BYTES>>>(query, ipw, ipb, nullptr);
    // 2) fused scores + exp + row-sum + AV (writes g_sh fp16, g_l, g_ctx)
    attn_fused<<<dim3(16, BH), 256, FUSED_SMEM_BYTES>>>();
    // 3) head-averaged attention weights (fp16 reads)
    avg_kernel<<<dim3(TT, BB), 256>>>(avg);
    // 4) out projection: [4096,1024] x [1024,1024]^T + bias -> d_out
    proj_gemm<1><<<dim3(1024 / 256, 4096 / 128), 256, PROJ_SMEM_BYTES>>>(nullptr, opw, opb, out);
}